// round 4
// baseline (speedup 1.0000x reference)
#include <cuda_runtime.h>
#include <cuda_bf16.h>

// StateSpaceLayer: out[b,t,r,c] = sum_{j<=t} A[r]^(t-j) * x[b,j,r,c]
// == per-(b,r,c) linear recurrence y_t = A[r]*y_{t-1} + x_t.
// x, out: (B,SEQ,D,D) fp32; A: (D,) fp32.  B=4, SEQ=512, D=64.
//
// R4: float2 vectorization with R2's occ-2 block shape.
// Block = one (b, r, c-half): 16 float2 lanes x 32 chunks of 16 timesteps.
// 512 threads, ~56 regs -> 2 blocks/SM so load/store phases of neighboring
// blocks overlap across the block-wide barriers.

#define SEQ   512
#define D     64
#define LCH   16            // timesteps per chunk (registers, float2)
#define NC    (SEQ/LCH)     // 32 chunks
#define CL2   16            // float2 c-lanes per block (half of 64 c)
#define TPB   (NC*CL2)      // 512 threads
#define TSTRIDE2 (D*D/2)    // timestep stride in float2 units = 2048

__global__ __launch_bounds__(TPB, 2)
void ssm_scan_kernel(const float2* __restrict__ x,
                     const float* __restrict__ A,
                     float2* __restrict__ out)
{
    // grid = B * D * 2 : block covers (b, r, c-half)
    const int bid   = blockIdx.x;
    const int chalf = bid & 1;
    const int r     = (bid >> 1) & (D - 1);
    const int b     = bid >> 7;

    const int tid = threadIdx.x;
    const int l   = tid & (CL2 - 1);     // float2 lane within half
    const int k   = tid >> 4;            // chunk index 0..NC-1
    const int lane2 = chalf * CL2 + l;   // float2 index within c-row (0..31)

    const float a = fmaxf(A[r], 1e-6f);  // reference clips at EPS=1e-6

    // element (b, k*LCH + i, r, 2*lane2) as float2 index
    const long base = ((long)(b * SEQ + k * LCH) * D + r) * (D / 2) + lane2;
    const float2* __restrict__ xp = x + base;

    // ---- load chunk: 16 independent streaming LDG.64 ----
    float2 v[LCH];
    #pragma unroll
    for (int i = 0; i < LCH; i++)
        v[i] = __ldcs(xp + (long)i * TSTRIDE2);

    // ---- local inclusive scan within chunk ----
    #pragma unroll
    for (int i = 1; i < LCH; i++) {
        v[i].x = fmaf(a, v[i - 1].x, v[i].x);
        v[i].y = fmaf(a, v[i - 1].y, v[i].y);
    }

    // ---- cross-chunk carry combine ----
    __shared__ float2 s_end[NC][CL2];
    __shared__ float2 s_pre[NC][CL2];
    s_end[k][l] = v[LCH - 1];
    __syncthreads();

    if (tid < CL2) {
        // a^16 via 4 squarings
        float a2  = a * a;
        float a4  = a2 * a2;
        float a8  = a4 * a4;
        float a16 = a8 * a8;
        float2 carry = make_float2(0.0f, 0.0f);
        #pragma unroll
        for (int kk = 0; kk < NC; kk++) {
            s_pre[kk][tid] = carry;                      // exclusive prefix
            float2 e = s_end[kk][tid];
            carry.x = fmaf(a16, carry.x, e.x);           // E_k = s_k + a^L * E_{k-1}
            carry.y = fmaf(a16, carry.y, e.y);
        }
    }
    __syncthreads();

    // ---- apply carry and store: out_i = v_i + a^(i+1) * E ----
    const float2 E = s_pre[k][l];
    float2* __restrict__ op = out + base;
    float pw = a;
    #pragma unroll
    for (int i = 0; i < LCH; i++) {
        float2 o;
        o.x = fmaf(pw, E.x, v[i].x);
        o.y = fmaf(pw, E.y, v[i].y);
        __stcs(op + (long)i * TSTRIDE2, o);
        pw *= a;
    }
}

extern "C" void kernel_launch(void* const* d_in, const int* in_sizes, int n_in,
                              void* d_out, int out_size)
{
    // Identify x vs A by element count (A has D=64 elements).
    const float* x = (const float*)d_in[0];
    const float* A = (const float*)d_in[1];
    long nx = in_sizes[0];
    if (n_in >= 2 && in_sizes[0] == D && in_sizes[1] > D) {
        x = (const float*)d_in[1];
        A = (const float*)d_in[0];
        nx = in_sizes[1];
    }
    const int B = (int)(nx / ((long)SEQ * D * D));   // 4

    dim3 grid(B * D * 2);
    dim3 block(TPB);
    ssm_scan_kernel<<<grid, block>>>((const float2*)x, A, (float2*)d_out);
}

// round 6
// speedup vs baseline: 1.4742x; 1.4742x over previous
#include <cuda_runtime.h>
#include <cuda_bf16.h>

// StateSpaceLayer: out[b,t,r,c] = sum_{j<=t} A[r]^(t-j) * x[b,j,r,c]
// == per-(b,r,c) linear recurrence y_t = A[r]*y_{t-1} + x_t.
// x, out: (B,SEQ,D,D) fp32; A: (D,) fp32.  B=4, SEQ=512, D=64.
//
// R6 (= R5 resubmitted after infra failure): R2's proven memory pattern
// (scalar LDG.32, warp = 32 contiguous c-lanes of one chunk, no cache hints)
// but LCH=16 with the sequence processed in two halves per block. Registers
// drop to ~40 -> occupancy 3 (48 warps/SM), so the load/combine/store phases
// of three blocks overlap. The combine warp carries its running prefix across
// the two halves in registers.

#define SEQ   512
#define D     64
#define LCH   16            // timesteps per chunk (registers)
#define NC    16            // chunks per sequence-half
#define HALF  (NC*LCH)      // 256 timesteps per half
#define CH    32            // c-lanes per block (half of D)
#define TPB   (NC*CH)       // 512 threads
#define TS    (D*D)         // timestep stride in floats

__global__ __launch_bounds__(TPB, 3)
void ssm_scan_kernel(const float* __restrict__ x,
                     const float* __restrict__ A,
                     float* __restrict__ out)
{
    // grid = B * D * 2 : block covers (b, r, c-half)
    const int bid   = blockIdx.x;
    const int chalf = bid & 1;
    const int r     = (bid >> 1) & (D - 1);
    const int b     = bid >> 7;

    const int tid = threadIdx.x;
    const int cl  = tid & (CH - 1);      // c-lane within half-row
    const int k   = tid >> 5;            // chunk index 0..NC-1

    const float a = fmaxf(A[r], 1e-6f);  // reference clips at EPS=1e-6

    // a^16 via 4 squarings (used by combine warp)
    const float a2  = a * a;
    const float a4  = a2 * a2;
    const float a8  = a4 * a4;
    const float a16 = a8 * a8;

    const long base0 = ((long)(b * SEQ + k * LCH) * D + r) * D + chalf * CH + cl;

    __shared__ float s_end[NC][CH];
    __shared__ float s_pre[NC][CH];

    float carry_reg = 0.0f;              // live only in combine warp (tid<32)

    #pragma unroll
    for (int h = 0; h < 2; h++) {
        const float* __restrict__ xp = x + base0 + (long)h * HALF * TS;

        // ---- load chunk: 16 independent coalesced LDG.32 ----
        float v[LCH];
        #pragma unroll
        for (int i = 0; i < LCH; i++)
            v[i] = xp[(long)i * TS];

        // ---- local inclusive scan ----
        #pragma unroll
        for (int i = 1; i < LCH; i++)
            v[i] = fmaf(a, v[i - 1], v[i]);

        // ---- cross-chunk carry combine ----
        s_end[k][cl] = v[LCH - 1];
        __syncthreads();

        if (tid < CH) {
            float c = carry_reg;
            #pragma unroll
            for (int kk = 0; kk < NC; kk++) {
                s_pre[kk][tid] = c;                    // exclusive prefix
                c = fmaf(a16, c, s_end[kk][tid]);      // E_k = s_k + a^L * E_{k-1}
            }
            carry_reg = c;                             // persists into next half
        }
        __syncthreads();

        // ---- apply carry and store: out_i = v_i + a^(i+1) * E ----
        const float E = s_pre[k][cl];
        float* __restrict__ op = out + base0 + (long)h * HALF * TS;
        float pw = a;
        #pragma unroll
        for (int i = 0; i < LCH; i++) {
            op[(long)i * TS] = fmaf(pw, E, v[i]);
            pw *= a;
        }
    }
}

extern "C" void kernel_launch(void* const* d_in, const int* in_sizes, int n_in,
                              void* d_out, int out_size)
{
    // Identify x vs A by element count (A has D=64 elements).
    const float* x = (const float*)d_in[0];
    const float* A = (const float*)d_in[1];
    long nx = in_sizes[0];
    if (n_in >= 2 && in_sizes[0] == D && in_sizes[1] > D) {
        x = (const float*)d_in[1];
        A = (const float*)d_in[0];
        nx = in_sizes[1];
    }
    const int B = (int)(nx / ((long)SEQ * D * D));   // 4

    dim3 grid(B * D * 2);
    dim3 block(TPB);
    ssm_scan_kernel<<<grid, block>>>(x, A, (float*)d_out);
}